// round 1
// baseline (speedup 1.0000x reference)
#include <cuda_runtime.h>
#include <cstdint>

#define NN 10000
#define NE 50000
#define WD 64
#define DEPTH 4
#define K2N 4096   // WD*WD

typedef unsigned long long u64;

// ---- packed fp32x2 helpers (Blackwell FFMA2 path, PTX-only) ----
__device__ __forceinline__ u64 pack2(float x, float y) {
    u64 r; asm("mov.b64 %0, {%1,%2};" : "=l"(r) : "f"(x), "f"(y)); return r;
}
__device__ __forceinline__ void unpack2(u64 v, float& x, float& y) {
    asm("mov.b64 {%0,%1}, %2;" : "=f"(x), "=f"(y) : "l"(v));
}
__device__ __forceinline__ void fma2(u64& d, u64 a, u64 b) {
    asm("fma.rn.f32x2 %0, %1, %2, %0;" : "+l"(d) : "l"(a), "l"(b));
}

// ---- scratch (device globals: allocation-free) ----
__device__ float g_ew[(size_t)NE * K2N];   // 819.2 MB per-edge matrices
__device__ float g_tT[WD * NE];            // relu(ea@k1+b1), TRANSPOSED [64][NE]
__device__ float g_h[2][NN * WD];          // ping-pong node features
__device__ float g_agg[NN * WD];           // scatter accumulator
__device__ float g_invd[NN];               // 1/max(indeg,1)
__device__ int   g_cnt[NN];

// ------------------------------------------------------------------
__global__ void k_zero() {
    int i = blockIdx.x * 256 + threadIdx.x;
    if (i < NN * WD) g_agg[i] = 0.f;
    if (i < NN) g_cnt[i] = 0;
}

// t = relu(edge_attr @ k1_W + k1_b), stored transposed; also in-degree counts
__global__ void k_edge(const float* __restrict__ ea, const int* __restrict__ ei,
                       const float* __restrict__ k1W, const float* __restrict__ k1b) {
    int i = blockIdx.x * 256 + threadIdx.x;
    if (i >= NE * WD) return;
    int e = i >> 6, o = i & 63;
    float a0 = ea[e * 3 + 0], a1 = ea[e * 3 + 1], a2 = ea[e * 3 + 2];
    float t = fmaf(a0, k1W[o], fmaf(a1, k1W[64 + o], fmaf(a2, k1W[128 + o], k1b[o])));
    g_tT[o * NE + e] = t > 0.f ? t : 0.f;
    if (o == 0) atomicAdd(&g_cnt[ei[NE + e]], 1);
}

// h0 = x @ fc1_W + fc1_b; inv_denom from counts
__global__ void k_node(const float* __restrict__ x, const float* __restrict__ W1,
                       const float* __restrict__ b1) {
    int i = blockIdx.x * 256 + threadIdx.x;
    if (i >= NN * WD) return;
    int n = i >> 6, o = i & 63;
    float v = fmaf(x[n * 3 + 0], W1[o],
              fmaf(x[n * 3 + 1], W1[64 + o],
              fmaf(x[n * 3 + 2], W1[128 + o], b1[o])));
    g_h[0][i] = v;
    if (o == 0) { int c = g_cnt[n]; g_invd[n] = 1.0f / (float)(c > 0 ? c : 1); }
}

// ew = t @ k2_W + k2_b   ([E,64] x [64,4096]) — packed-f32x2 tiled GEMM
// Tile: 128 edges x 128 cols, K=64 (full). 256 threads, micro-tile 8x8.
#define EW_BM 128
#define EW_BN 128
__global__ void k_ew(const float* __restrict__ k2W, const float* __restrict__ k2b) {
    extern __shared__ float sm[];
    float* sAT = sm;               // [64][132] transposed A (pad 132: 16B-aligned, bank-clean)
    float* sB  = sm + 64 * 132;    // [64][128]
    int e0 = blockIdx.x * EW_BM;
    int c0 = blockIdx.y * EW_BN;
    int tid = threadIdx.x;

    for (int i = tid; i < 64 * EW_BM; i += 256) {
        int k = i >> 7, r = i & 127;
        int e = e0 + r;
        sAT[k * 132 + r] = (e < NE) ? g_tT[k * NE + e] : 0.f;
    }
    for (int i = tid; i < 64 * EW_BN; i += 256) {
        int k = i >> 7, j = i & 127;
        sB[k * 128 + j] = k2W[k * K2N + c0 + j];
    }
    __syncthreads();

    int tx = tid & 15, ty = tid >> 4;
    u64 acc[8][4];
#pragma unroll
    for (int r = 0; r < 8; r++)
#pragma unroll
        for (int p = 0; p < 4; p++) acc[r][p] = 0ull;

    const float* aptr = sAT + ty * 8;
    const float* bptr = sB + tx * 4;
#pragma unroll 4
    for (int k = 0; k < 64; k++) {
        float4 bl = *(const float4*)(bptr + k * 128);
        float4 bh = *(const float4*)(bptr + k * 128 + 64);
        u64 b0 = pack2(bl.x, bl.y), b1 = pack2(bl.z, bl.w);
        u64 b2 = pack2(bh.x, bh.y), b3 = pack2(bh.z, bh.w);
        float4 a0 = *(const float4*)(aptr + k * 132);
        float4 a1 = *(const float4*)(aptr + k * 132 + 4);
        float ar[8] = {a0.x, a0.y, a0.z, a0.w, a1.x, a1.y, a1.z, a1.w};
#pragma unroll
        for (int r = 0; r < 8; r++) {
            u64 aa = pack2(ar[r], ar[r]);
            fma2(acc[r][0], aa, b0);
            fma2(acc[r][1], aa, b1);
            fma2(acc[r][2], aa, b2);
            fma2(acc[r][3], aa, b3);
        }
    }

    float4 bb0 = *(const float4*)(k2b + c0 + tx * 4);
    float4 bb1 = *(const float4*)(k2b + c0 + 64 + tx * 4);
#pragma unroll
    for (int r = 0; r < 8; r++) {
        int e = e0 + ty * 8 + r;
        if (e >= NE) break;
        float v0, v1, v2, v3, w0, w1, w2, w3;
        unpack2(acc[r][0], v0, v1); unpack2(acc[r][1], v2, v3);
        unpack2(acc[r][2], w0, w1); unpack2(acc[r][3], w2, w3);
        float4 outl = {v0 + bb0.x, v1 + bb0.y, v2 + bb0.z, v3 + bb0.w};
        float4 outh = {w0 + bb1.x, w1 + bb1.y, w2 + bb1.z, w3 + bb1.w};
        float* dst = g_ew + (size_t)e * K2N + c0;
        *(float4*)(dst + tx * 4) = outl;
        *(float4*)(dst + 64 + tx * 4) = outh;
    }
}

// msg[e] = ew[e]^T h[src[e]]; scatter-add into agg[dst]. Warp per edge. HBM-bound.
__global__ void k_msg(const int* __restrict__ ei, int cur) {
    int warp = threadIdx.x >> 5, lane = threadIdx.x & 31;
    int e = blockIdx.x * 8 + warp;
    if (e >= NE) return;
    int src = ei[e], dst = ei[NE + e];
    __shared__ float sh[8][64];
    const float* h = g_h[cur];
    sh[warp][lane] = h[src * 64 + lane];
    sh[warp][32 + lane] = h[src * 64 + 32 + lane];
    __syncwarp();
    const u64* wrow = (const u64*)(g_ew + (size_t)e * K2N) + lane; // (i*64 + 2*lane)/2
    u64 acc0 = 0ull, acc1 = 0ull;
#pragma unroll
    for (int i = 0; i < 64; i += 2) {
        u64 h0 = pack2(sh[warp][i], sh[warp][i]);
        u64 h1 = pack2(sh[warp][i + 1], sh[warp][i + 1]);
        fma2(acc0, h0, wrow[i * 32]);
        fma2(acc1, h1, wrow[(i + 1) * 32]);
    }
    float m0, m1, m2, m3;
    unpack2(acc0, m0, m1); unpack2(acc1, m2, m3);
    float* ag = g_agg + dst * 64 + 2 * lane;
    atomicAdd(ag, m0 + m2);
    atomicAdd(ag + 1, m1 + m3);
}

// h' = relu(agg*invd + h@root + conv_b); also re-zero agg for next iter
__global__ void k_update(const float* __restrict__ root, const float* __restrict__ cb, int cur) {
    __shared__ float srt[64 * 64];
    __shared__ float shh[4][64];
    int tid = threadIdx.x;
    int n0 = blockIdx.x * 4;
    for (int i = tid; i < 4096; i += 256) srt[i] = root[i];
    int nl = tid >> 6, o = tid & 63;
    int n = n0 + nl;                       // NN % 4 == 0, no guard needed
    const float* h = g_h[cur];
    shh[nl][o] = h[n * 64 + o];
    __syncthreads();
    float acc = g_agg[n * 64 + o] * g_invd[n];
    g_agg[n * 64 + o] = 0.f;
#pragma unroll
    for (int i = 0; i < 64; i++) acc = fmaf(shh[nl][i], srt[i * 64 + o], acc);
    acc += cb[o];
    g_h[cur ^ 1][n * 64 + o] = acc > 0.f ? acc : 0.f;
}

// out = h @ fc2_W + fc2_b   (warp per node)
__global__ void k_out(const float* __restrict__ w2, const float* __restrict__ b2,
                      float* __restrict__ out, int cur) {
    int warp = threadIdx.x >> 5, lane = threadIdx.x & 31;
    int n = blockIdx.x * 8 + warp;
    if (n >= NN) return;
    const float* h = g_h[cur] + n * 64;
    float s = h[lane] * w2[lane] + h[32 + lane] * w2[32 + lane];
#pragma unroll
    for (int d = 16; d; d >>= 1) s += __shfl_xor_sync(0xffffffff, s, d);
    if (lane == 0) out[n] = s + b2[0];
}

// ------------------------------------------------------------------
extern "C" void kernel_launch(void* const* d_in, const int* in_sizes, int n_in,
                              void* d_out, int out_size) {
    const float* x    = (const float*)d_in[0];
    const int*   ei   = (const int*)  d_in[1];
    const float* ea   = (const float*)d_in[2];
    const float* fc1W = (const float*)d_in[3];
    const float* fc1b = (const float*)d_in[4];
    const float* k1W  = (const float*)d_in[5];
    const float* k1b  = (const float*)d_in[6];
    const float* k2W  = (const float*)d_in[7];
    const float* k2b  = (const float*)d_in[8];
    const float* root = (const float*)d_in[9];
    const float* cb   = (const float*)d_in[10];
    const float* fc2W = (const float*)d_in[11];
    const float* fc2b = (const float*)d_in[12];
    float* out = (float*)d_out;

    cudaFuncSetAttribute(k_ew, cudaFuncAttributeMaxDynamicSharedMemorySize, 68 * 1024);

    k_zero<<<(NN * WD + 255) / 256, 256>>>();
    k_edge<<<(NE * WD + 255) / 256, 256>>>(ea, ei, k1W, k1b);
    k_node<<<(NN * WD + 255) / 256, 256>>>(x, fc1W, fc1b);

    dim3 gew((NE + EW_BM - 1) / EW_BM, K2N / EW_BN);
    k_ew<<<gew, 256, (64 * 132 + 64 * 128) * 4>>>(k2W, k2b);

    int cur = 0;
    for (int d = 0; d < DEPTH; d++) {
        k_msg<<<(NE + 7) / 8, 256>>>(ei, cur);
        k_update<<<NN / 4, 256>>>(root, cb, cur);
        cur ^= 1;
    }
    k_out<<<(NN + 7) / 8, 256>>>(fc2W, fc2b, out, cur);
}